// round 3
// baseline (speedup 1.0000x reference)
#include <cuda_runtime.h>
#include <cuda_bf16.h>
#include <float.h>
#include <stdint.h>

typedef __nv_bfloat16 bf16;

#define T_SEQ   4096
#define DIM     768
#define HEADS   12
#define HEAD_D  64
#define N_QKV   (3 * DIM)
#define RMS_EPS 1.1920928955078125e-07f
#define ATTN_SCALE 0.12f

// ---------------- scratch ----------------------------------------------------
__device__ float g_qkv[3 * HEADS * T_SEQ * HEAD_D];
__device__ bf16  g_sp_hi[3 * HEADS * T_SEQ * HEAD_D];
__device__ bf16  g_sp_lo[3 * HEADS * T_SEQ * HEAD_D];
__device__ bf16  g_xh[T_SEQ * DIM],  g_xl[T_SEQ * DIM];
__device__ bf16  g_wqh[N_QKV * DIM], g_wql[N_QKV * DIM];
__device__ bf16  g_wph[DIM * DIM],   g_wpl[DIM * DIM];
__device__ bf16  g_yh[T_SEQ * DIM],  g_yl[T_SEQ * DIM];

// ---------------- helpers ----------------------------------------------------
__device__ __forceinline__ uint32_t smem_u32(const void* p) {
    return (uint32_t)__cvta_generic_to_shared(p);
}
__device__ __forceinline__ void cp16(void* dst, const void* src) {
    asm volatile("cp.async.cg.shared.global [%0], [%1], 16;\n"
                 :: "r"(smem_u32(dst)), "l"(src));
}
__device__ __forceinline__ void cp_commit() { asm volatile("cp.async.commit_group;\n"); }
template<int N>
__device__ __forceinline__ void cp_wait() { asm volatile("cp.async.wait_group %0;\n" :: "n"(N)); }

__device__ __forceinline__ void ldsm_x4(uint32_t& r0, uint32_t& r1,
                                        uint32_t& r2, uint32_t& r3, uint32_t a) {
    asm volatile("ldmatrix.sync.aligned.m8n8.x4.shared.b16 {%0,%1,%2,%3},[%4];\n"
                 : "=r"(r0), "=r"(r1), "=r"(r2), "=r"(r3) : "r"(a));
}
__device__ __forceinline__ void ldsm_x4_t(uint32_t& r0, uint32_t& r1,
                                          uint32_t& r2, uint32_t& r3, uint32_t a) {
    asm volatile("ldmatrix.sync.aligned.m8n8.x4.trans.shared.b16 {%0,%1,%2,%3},[%4];\n"
                 : "=r"(r0), "=r"(r1), "=r"(r2), "=r"(r3) : "r"(a));
}
__device__ __forceinline__ void mma16816(float* d, const uint32_t* a, const uint32_t* b) {
    asm volatile(
        "mma.sync.aligned.m16n8k16.row.col.f32.bf16.bf16.f32 "
        "{%0,%1,%2,%3},{%4,%5,%6,%7},{%8,%9},{%0,%1,%2,%3};\n"
        : "+f"(d[0]), "+f"(d[1]), "+f"(d[2]), "+f"(d[3])
        : "r"(a[0]), "r"(a[1]), "r"(a[2]), "r"(a[3]), "r"(b[0]), "r"(b[1]));
}
__device__ __forceinline__ uint32_t pack_bf2(float x, float y) {
    __nv_bfloat162 t = __floats2bfloat162_rn(x, y);
    return *(uint32_t*)&t;
}
__device__ __forceinline__ void split_f(float v, bf16& h, bf16& l) {
    h = __float2bfloat16(v);
    l = __float2bfloat16(v - __bfloat162float(h));
}

__global__ void split_kernel(const float* __restrict__ in,
                             bf16* __restrict__ hi, bf16* __restrict__ lo, int n) {
    int i = blockIdx.x * blockDim.x + threadIdx.x;
    if (i < n) { bf16 h, l; split_f(in[i], h, l); hi[i] = h; lo[i] = l; }
}

// ---------------- GEMM: C = A @ B^T, 3-term, cp.async 2-stage ----------------
// Block tile 128x64, 256 thr, warps 4(m) x 2(n), warp tile 32x32. BK=32.
#define LDA 40
#define GA_ELEMS (2 * 128 * LDA)           // hi+lo A per stage
#define GB_ELEMS (2 * 64 * LDA)
#define GSTAGE   (GA_ELEMS + GB_ELEMS)     // 15360 elems = 30720 B

template<int MODE>
__global__ __launch_bounds__(256) void gemm_mma_kernel(
    const bf16* __restrict__ Ah, const bf16* __restrict__ Al,
    const bf16* __restrict__ Bh, const bf16* __restrict__ Bl,
    float* __restrict__ C)
{
    constexpr int K = 768;
    constexpr int NK = K / 32;
    extern __shared__ bf16 sm[];
    const int tid = threadIdx.x;
    const int wid = tid >> 5, lane = tid & 31;
    const int wm = wid & 3, wn = wid >> 2;
    const int m0 = blockIdx.x * 128, n0 = blockIdx.y * 64;
    const int g = lane >> 2, q = lane & 3;

    auto prefetch = [&](int st, int k0) {
        bf16* base = sm + st * GSTAGE;
        // A: per hl 512 chunks of 16B; thread does chunks tid, tid+256
        #pragma unroll
        for (int i = 0; i < 2; i++) {
            int c = tid + i * 256;
            int r = c >> 2, col = (c & 3) * 8;
            size_t go = (size_t)(m0 + r) * K + k0 + col;
            cp16(base + 0 * 128 * LDA + r * LDA + col, Ah + go);
            cp16(base + 1 * 128 * LDA + r * LDA + col, Al + go);
        }
        // B: per hl 256 chunks
        {
            int r = tid >> 2, col = (tid & 3) * 8;
            size_t go = (size_t)(n0 + r) * K + k0 + col;
            cp16(base + GA_ELEMS + 0 * 64 * LDA + r * LDA + col, Bh + go);
            cp16(base + GA_ELEMS + 1 * 64 * LDA + r * LDA + col, Bl + go);
        }
    };

    float acc[2][4][4];
    #pragma unroll
    for (int a = 0; a < 2; a++)
        #pragma unroll
        for (int b = 0; b < 4; b++)
            #pragma unroll
            for (int c = 0; c < 4; c++) acc[a][b][c] = 0.f;

    prefetch(0, 0);
    cp_commit();

    for (int k = 0; k < NK; k++) {
        if (k + 1 < NK) { prefetch((k + 1) & 1, (k + 1) * 32); cp_commit(); cp_wait<1>(); }
        else cp_wait<0>();
        __syncthreads();

        bf16* base = sm + (k & 1) * GSTAGE;
        bf16 (*sA)[128][LDA] = (bf16(*)[128][LDA])base;
        bf16 (*sB)[64][LDA]  = (bf16(*)[64][LDA])(base + GA_ELEMS);

        uint32_t aF[2][2][2][4];
        uint32_t bF[2][4][2][2];
        #pragma unroll
        for (int v = 0; v < 2; v++) {
            #pragma unroll
            for (int mt = 0; mt < 2; mt++)
                #pragma unroll
                for (int kt = 0; kt < 2; kt++) {
                    uint32_t ad = smem_u32(&sA[v][wm * 32 + mt * 16 + (lane & 15)]
                                              [kt * 16 + (lane >> 4) * 8]);
                    ldsm_x4(aF[v][mt][kt][0], aF[v][mt][kt][1],
                            aF[v][mt][kt][2], aF[v][mt][kt][3], ad);
                }
            #pragma unroll
            for (int np = 0; np < 2; np++)
                #pragma unroll
                for (int kt = 0; kt < 2; kt++) {
                    uint32_t ad = smem_u32(&sB[v][wn * 32 + np * 16 + (lane & 15)]
                                              [kt * 16 + (lane >> 4) * 8]);
                    uint32_t r0, r1, r2, r3;
                    ldsm_x4(r0, r1, r2, r3, ad);
                    bF[v][np * 2 + 0][kt][0] = r0; bF[v][np * 2 + 1][kt][0] = r1;
                    bF[v][np * 2 + 0][kt][1] = r2; bF[v][np * 2 + 1][kt][1] = r3;
                }
        }
        #pragma unroll
        for (int mt = 0; mt < 2; mt++)
            #pragma unroll
            for (int nt = 0; nt < 4; nt++)
                #pragma unroll
                for (int kt = 0; kt < 2; kt++) {
                    mma16816(acc[mt][nt], aF[0][mt][kt], bF[0][nt][kt]);
                    mma16816(acc[mt][nt], aF[0][mt][kt], bF[1][nt][kt]);
                    mma16816(acc[mt][nt], aF[1][mt][kt], bF[0][nt][kt]);
                }
        __syncthreads();
    }

    #pragma unroll
    for (int mt = 0; mt < 2; mt++)
        #pragma unroll
        for (int nt = 0; nt < 4; nt++) {
            int r0 = m0 + wm * 32 + mt * 16 + g;
            int cc = n0 + wn * 32 + nt * 8 + q * 2;
            float* a = acc[mt][nt];
            if (MODE == 0) {
                size_t base = (size_t)(cc >> 6) * (T_SEQ * HEAD_D) + (cc & 63);
                *(float2*)&g_qkv[base + (size_t)r0 * HEAD_D]       = make_float2(a[0], a[1]);
                *(float2*)&g_qkv[base + (size_t)(r0 + 8) * HEAD_D] = make_float2(a[2], a[3]);
            } else {
                *(float2*)&C[(size_t)r0 * DIM + cc]       = make_float2(a[0], a[1]);
                *(float2*)&C[(size_t)(r0 + 8) * DIM + cc] = make_float2(a[2], a[3]);
            }
        }
}

// ---------------- RMSNorm + rotary + split -----------------------------------
__global__ void rms_rope_split_kernel() {
    const int t = blockIdx.x;
    const int comp = blockIdx.y;
    const int h = threadIdx.x >> 5;
    const int lane = threadIdx.x & 31;
    const size_t off = ((size_t)(comp * HEADS + h)) * (T_SEQ * HEAD_D) + (size_t)t * HEAD_D;
    const float* p = g_qkv + off;
    float v0 = p[lane], v1 = p[lane + 32];

    if (comp < 2) {
        float ss = v0 * v0 + v1 * v1;
        #pragma unroll
        for (int o = 16; o >= 1; o >>= 1) ss += __shfl_xor_sync(0xffffffffu, ss, o);
        float r = rsqrtf(ss * (1.0f / HEAD_D) + RMS_EPS);
        v0 *= r; v1 *= r;
        if (lane < 16) {
            float fr = exp2f(-10.0f * (float)lane / 15.0f);
            float th = (float)t * fr, s, c;
            sincosf(th, &s, &c);
            float y0 =  v0 * c + v1 * s;
            float y1 = -v0 * s + v1 * c;
            v0 = y0; v1 = y1;
        }
        if (comp == 0) { v0 *= ATTN_SCALE; v1 *= ATTN_SCALE; }
    }
    bf16 h0, l0, h1, l1;
    split_f(v0, h0, l0);
    split_f(v1, h1, l1);
    g_sp_hi[off + lane] = h0;      g_sp_lo[off + lane] = l0;
    g_sp_hi[off + lane + 32] = h1; g_sp_lo[off + lane + 32] = l1;
}

// ---------------- Flash attention, BM=128, cp.async 2-stage ------------------
#define FLD 72
#define FK_ELEMS (2 * 64 * FLD)            // hi+lo K per stage
#define FSTAGE   (2 * FK_ELEMS)            // K + V = 18432 elems = 36864 B

__global__ __launch_bounds__(256) void flash_mma_kernel() {
    extern __shared__ bf16 fsm[];
    const int qb = (gridDim.x - 1) - blockIdx.x;   // heavy first
    const int h = blockIdx.y;
    const int tid = threadIdx.x, wid = tid >> 5, lane = tid & 31;
    const int g = lane >> 2, q = lane & 3;

    const size_t HS = (size_t)T_SEQ * HEAD_D;
    const bf16* Qh = g_sp_hi + (0 * HEADS + h) * HS;
    const bf16* Ql = g_sp_lo + (0 * HEADS + h) * HS;
    const bf16* Kh = g_sp_hi + (1 * HEADS + h) * HS;
    const bf16* Kl = g_sp_lo + (1 * HEADS + h) * HS;
    const bf16* Vh = g_sp_hi + (2 * HEADS + h) * HS;
    const bf16* Vl = g_sp_lo + (2 * HEADS + h) * HS;

    const int nk = 2 * qb + 2;             // number of 64-wide K tiles

    auto prefetch = [&](int st, int kb) {
        bf16* base = fsm + st * FSTAGE;
        // 4 arrays (Kh,Kl,Vh,Vl), each 64x64: 512 16B-chunks; thread does 2 per array
        #pragma unroll
        for (int i = 0; i < 2; i++) {
            int c = tid + i * 256;
            int r = c >> 3, col = (c & 7) * 8;
            size_t go = (size_t)(kb * 64 + r) * HEAD_D + col;
            cp16(base + 0 * 64 * FLD + r * FLD + col, Kh + go);
            cp16(base + 1 * 64 * FLD + r * FLD + col, Kl + go);
            cp16(base + FK_ELEMS + 0 * 64 * FLD + r * FLD + col, Vh + go);
            cp16(base + FK_ELEMS + 1 * 64 * FLD + r * FLD + col, Vl + go);
        }
    };

    // Q fragments from global
    uint32_t qF[2][4][4];
    {
        int r0 = qb * 128 + wid * 16 + g;
        #pragma unroll
        for (int v = 0; v < 2; v++) {
            const bf16* Qp = v ? Ql : Qh;
            #pragma unroll
            for (int kt = 0; kt < 4; kt++) {
                int c = kt * 16 + q * 2;
                qF[v][kt][0] = *(const uint32_t*)(Qp + (size_t)r0 * HEAD_D + c);
                qF[v][kt][1] = *(const uint32_t*)(Qp + (size_t)(r0 + 8) * HEAD_D + c);
                qF[v][kt][2] = *(const uint32_t*)(Qp + (size_t)r0 * HEAD_D + c + 8);
                qF[v][kt][3] = *(const uint32_t*)(Qp + (size_t)(r0 + 8) * HEAD_D + c + 8);
            }
        }
    }

    float o[8][4];
    #pragma unroll
    for (int i = 0; i < 8; i++)
        #pragma unroll
        for (int j = 0; j < 4; j++) o[i][j] = 0.f;
    float m0_ = -1e30f, m1_ = -1e30f, l0_ = 0.f, l1_ = 0.f;

    prefetch(0, 0);
    cp_commit();

    for (int kb = 0; kb < nk; kb++) {
        if (kb + 1 < nk) { prefetch((kb + 1) & 1, kb + 1); cp_commit(); cp_wait<1>(); }
        else cp_wait<0>();
        __syncthreads();

        bf16* base = fsm + (kb & 1) * FSTAGE;
        bf16 (*sK)[64][FLD] = (bf16(*)[64][FLD])base;
        bf16 (*sV)[64][FLD] = (bf16(*)[64][FLD])(base + FK_ELEMS);

        // ---- S = Q K^T ----
        float s[8][4];
        #pragma unroll
        for (int i = 0; i < 8; i++)
            #pragma unroll
            for (int j = 0; j < 4; j++) s[i][j] = 0.f;

        #pragma unroll
        for (int kt = 0; kt < 4; kt++) {
            uint32_t bh[8][2], bl[8][2];
            #pragma unroll
            for (int np = 0; np < 4; np++) {
                uint32_t ad = smem_u32(&sK[0][np * 16 + (lane & 15)]
                                          [kt * 16 + (lane >> 4) * 8]);
                uint32_t r0, r1, r2, r3;
                ldsm_x4(r0, r1, r2, r3, ad);
                bh[np * 2][0] = r0; bh[np * 2 + 1][0] = r1;
                bh[np * 2][1] = r2; bh[np * 2 + 1][1] = r3;
                ad = smem_u32(&sK[1][np * 16 + (lane & 15)]
                                  [kt * 16 + (lane >> 4) * 8]);
                ldsm_x4(r0, r1, r2, r3, ad);
                bl[np * 2][0] = r0; bl[np * 2 + 1][0] = r1;
                bl[np * 2][1] = r2; bl[np * 2 + 1][1] = r3;
            }
            #pragma unroll
            for (int nt = 0; nt < 8; nt++) {
                mma16816(s[nt], qF[0][kt], bh[nt]);
                mma16816(s[nt], qF[0][kt], bl[nt]);
                mma16816(s[nt], qF[1][kt], bh[nt]);
            }
        }

        // ---- causal mask (only the two diagonal tiles need it) ----
        if (kb >= 2 * qb) {
            int rl0 = wid * 16 + g, rl1 = rl0 + 8;
            int cbase = (kb - 2 * qb) * 64;
            #pragma unroll
            for (int nt = 0; nt < 8; nt++) {
                int c0 = cbase + nt * 8 + q * 2, c1 = c0 + 1;
                if (c0 > rl0) s[nt][0] = -1e30f;
                if (c1 > rl0) s[nt][1] = -1e30f;
                if (c0 > rl1) s[nt][2] = -1e30f;
                if (c1 > rl1) s[nt][3] = -1e30f;
            }
        }

        // ---- online softmax ----
        float mt0 = -1e30f, mt1 = -1e30f;
        #pragma unroll
        for (int nt = 0; nt < 8; nt++) {
            mt0 = fmaxf(mt0, fmaxf(s[nt][0], s[nt][1]));
            mt1 = fmaxf(mt1, fmaxf(s[nt][2], s[nt][3]));
        }
        mt0 = fmaxf(mt0, __shfl_xor_sync(0xffffffffu, mt0, 1));
        mt0 = fmaxf(mt0, __shfl_xor_sync(0xffffffffu, mt0, 2));
        mt1 = fmaxf(mt1, __shfl_xor_sync(0xffffffffu, mt1, 1));
        mt1 = fmaxf(mt1, __shfl_xor_sync(0xffffffffu, mt1, 2));

        float mn0 = fmaxf(m0_, mt0), mn1 = fmaxf(m1_, mt1);
        float al0 = __expf(m0_ - mn0), al1 = __expf(m1_ - mn1);
        m0_ = mn0; m1_ = mn1;

        float rs0 = 0.f, rs1 = 0.f;
        #pragma unroll
        for (int nt = 0; nt < 8; nt++) {
            s[nt][0] = __expf(s[nt][0] - mn0);
            s[nt][1] = __expf(s[nt][1] - mn0);
            s[nt][2] = __expf(s[nt][2] - mn1);
            s[nt][3] = __expf(s[nt][3] - mn1);
            rs0 += s[nt][0] + s[nt][1];
            rs1 += s[nt][2] + s[nt][3];
        }
        rs0 += __shfl_xor_sync(0xffffffffu, rs0, 1);
        rs0 += __shfl_xor_sync(0xffffffffu, rs0, 2);
        rs1 += __shfl_xor_sync(0xffffffffu, rs1, 1);
        rs1 += __shfl_xor_sync(0xffffffffu, rs1, 2);
        l0_ = l0_ * al0 + rs0;
        l1_ = l1_ * al1 + rs1;
        #pragma unroll
        for (int nt = 0; nt < 8; nt++) {
            o[nt][0] *= al0; o[nt][1] *= al0;
            o[nt][2] *= al1; o[nt][3] *= al1;
        }

        // ---- P -> a-fragments ----
        uint32_t pF[2][4][4];
        #pragma unroll
        for (int kt = 0; kt < 4; kt++) {
            #pragma unroll
            for (int half = 0; half < 2; half++) {
                float p0 = s[2 * kt + half][0], p1 = s[2 * kt + half][1];
                float p2 = s[2 * kt + half][2], p3 = s[2 * kt + half][3];
                float h0 = __bfloat162float(__float2bfloat16(p0));
                float h1 = __bfloat162float(__float2bfloat16(p1));
                float h2 = __bfloat162float(__float2bfloat16(p2));
                float h3 = __bfloat162float(__float2bfloat16(p3));
                pF[0][kt][0 + 2 * half] = pack_bf2(h0, h1);
                pF[0][kt][1 + 2 * half] = pack_bf2(h2, h3);
                pF[1][kt][0 + 2 * half] = pack_bf2(p0 - h0, p1 - h1);
                pF[1][kt][1 + 2 * half] = pack_bf2(p2 - h2, p3 - h3);
            }
        }

        // ---- O += P V ----
        #pragma unroll
        for (int kt = 0; kt < 4; kt++) {
            uint32_t bvh[8][2], bvl[8][2];
            #pragma unroll
            for (int np = 0; np < 4; np++) {
                uint32_t ad = smem_u32(&sV[0][kt * 16 + (lane & 15)]
                                          [np * 16 + (lane >> 4) * 8]);
                uint32_t r0, r1, r2, r3;
                ldsm_x4_t(r0, r1, r2, r3, ad);
                bvh[np * 2][0] = r0; bvh[np * 2][1] = r1;
                bvh[np * 2 + 1][0] = r2; bvh[np * 2 + 1][1] = r3;
                ad = smem_u32(&sV[1][kt * 16 + (lane & 15)]
                                  [np * 16 + (lane >> 4) * 8]);
                ldsm_x4_t(r0, r1, r2, r3, ad);
                bvl[np * 2][0] = r0; bvl[np * 2][1] = r1;
                bvl[np * 2 + 1][0] = r2; bvl[np * 2 + 1][1] = r3;
            }
            #pragma unroll
            for (int nt = 0; nt < 8; nt++) {
                mma16816(o[nt], pF[0][kt], bvh[nt]);
                mma16816(o[nt], pF[0][kt], bvl[nt]);
                mma16816(o[nt], pF[1][kt], bvh[nt]);
            }
        }
        __syncthreads();
    }

    // ---- epilogue ----
    float i0 = 1.f / l0_, i1 = 1.f / l1_;
    int t0 = qb * 128 + wid * 16 + g;
    #pragma unroll
    for (int nt = 0; nt < 8; nt++) {
        int d = h * HEAD_D + nt * 8 + q * 2;
        float y0 = o[nt][0] * i0, y1 = o[nt][1] * i0;
        float y2 = o[nt][2] * i1, y3 = o[nt][3] * i1;
        float h0 = __bfloat162float(__float2bfloat16(y0));
        float h1 = __bfloat162float(__float2bfloat16(y1));
        float h2 = __bfloat162float(__float2bfloat16(y2));
        float h3 = __bfloat162float(__float2bfloat16(y3));
        *(uint32_t*)&g_yh[(size_t)t0 * DIM + d]       = pack_bf2(h0, h1);
        *(uint32_t*)&g_yh[(size_t)(t0 + 8) * DIM + d] = pack_bf2(h2, h3);
        *(uint32_t*)&g_yl[(size_t)t0 * DIM + d]       = pack_bf2(y0 - h0, y1 - h1);
        *(uint32_t*)&g_yl[(size_t)(t0 + 8) * DIM + d] = pack_bf2(y2 - h2, y3 - h3);
    }
}

// ---------------------------------------------------------------------------
extern "C" void kernel_launch(void* const* d_in, const int* in_sizes, int n_in,
                              void* d_out, int out_size)
{
    const float* x        = (const float*)d_in[0];
    const float* qkv_w    = (const float*)d_in[1];
    const float* c_proj_w = (const float*)d_in[2];
    float* out            = (float*)d_out;

    bf16 *xh, *xl, *wqh, *wql, *wph, *wpl, *yh, *yl;
    cudaGetSymbolAddress((void**)&xh,  g_xh);  cudaGetSymbolAddress((void**)&xl,  g_xl);
    cudaGetSymbolAddress((void**)&wqh, g_wqh); cudaGetSymbolAddress((void**)&wql, g_wql);
    cudaGetSymbolAddress((void**)&wph, g_wph); cudaGetSymbolAddress((void**)&wpl, g_wpl);
    cudaGetSymbolAddress((void**)&yh,  g_yh);  cudaGetSymbolAddress((void**)&yl,  g_yl);

    {
        int n1 = T_SEQ * DIM, n2 = N_QKV * DIM, n3 = DIM * DIM;
        split_kernel<<<(n1 + 255) / 256, 256>>>(x, xh, xl, n1);
        split_kernel<<<(n2 + 255) / 256, 256>>>(qkv_w, wqh, wql, n2);
        split_kernel<<<(n3 + 255) / 256, 256>>>(c_proj_w, wph, wpl, n3);
    }

    const int gemm_smem = 2 * GSTAGE * sizeof(bf16);    // 61440 B
    cudaFuncSetAttribute(gemm_mma_kernel<0>,
                         cudaFuncAttributeMaxDynamicSharedMemorySize, gemm_smem);
    cudaFuncSetAttribute(gemm_mma_kernel<1>,
                         cudaFuncAttributeMaxDynamicSharedMemorySize, gemm_smem);

    gemm_mma_kernel<0><<<dim3(T_SEQ / 128, N_QKV / 64), 256, gemm_smem>>>(
        xh, xl, wqh, wql, nullptr);

    rms_rope_split_kernel<<<dim3(T_SEQ, 3), HEADS * 32>>>();

    const int flash_smem = 2 * FSTAGE * sizeof(bf16);   // 73728 B
    cudaFuncSetAttribute(flash_mma_kernel,
                         cudaFuncAttributeMaxDynamicSharedMemorySize, flash_smem);
    flash_mma_kernel<<<dim3(T_SEQ / 128, HEADS), 256, flash_smem>>>();

    gemm_mma_kernel<1><<<dim3(T_SEQ / 128, DIM / 64), 256, gemm_smem>>>(
        yh, yl, wph, wpl, out);
}